// round 13
// baseline (speedup 1.0000x reference)
#include <cuda_runtime.h>

// SocialCircleLayer: B=8192 rows, N=128 neighbors, T=8, P=8.
// R13: R12 two-kernel design with the gather-index bug fixed:
// __ffs(mq|1u) always returned bit 0 -> wrong lanes summed (rel_err 0.416).
// Now: j = mq ? 8r + ffs(mq)-1 : 0 (convergent shuffles, guarded accumulate).
//  K1: pure streaming, no smem/no barrier. Warp-internal bucketed reduction
//      (8 ballots -> quarter-split ffs/shfl gather -> width-4 tree); leaders
//      store one coalesced 128B float4 partial per warp to __device__ scratch.
//  K2: combine 4 warp-partials per row (512B coalesced), divide, 96B store.

#define NNEI   128
#define PARTS  8
#define MU_F     1e-4f
#define CEPS_F   1e-4f
#define TWO_PI_F 6.283185307179586f
#define PI_F     3.14159265358979f
#define PIO2_F   1.5707963267949f
#define PIO4_F   0.78539816339745f
#define TAN_PIO8 0.41421356237f
#define MAX_B  8192

__device__ float4 g_scratch[MAX_B * 32];   // [B][4 warps][8 parts]

__device__ __forceinline__ float approx_len(float x2) {
    float r;
    asm("rsqrt.approx.f32 %0, %1;" : "=f"(r) : "f"(x2));
    float len = x2 * r;
    return (x2 > 0.0f) ? len : 0.0f;
}

// atan2 in [0, 2*pi): |err| < ~3e-7 rad (validated R11: rel_err 6.8e-8).
__device__ __forceinline__ float atan2_2pi(float y, float x) {
    const float ax = fabsf(x);
    const float ay = fabsf(y);
    const float mx = fmaxf(ax, ay);
    const float mn = fminf(ax, ay);
    float t = (mx == 0.0f) ? 0.0f : __fdividef(mn, mx);

    const bool red = (t > TAN_PIO8);
    const float u  = red ? __fdividef(t - 1.0f, t + 1.0f) : t;

    const float z = u * u;
    float q;
    q = -1.0f / 15.0f;
    q = fmaf(q, z,  1.0f / 13.0f);
    q = fmaf(q, z, -1.0f / 11.0f);
    q = fmaf(q, z,  1.0f /  9.0f);
    q = fmaf(q, z, -1.0f /  7.0f);
    q = fmaf(q, z,  1.0f /  5.0f);
    q = fmaf(q, z, -1.0f /  3.0f);
    float a = fmaf(q * z, u, u);          // atan(u)

    if (red)      a += PIO4_F;
    if (ay > ax)  a = PIO2_F - a;
    if (x < 0.0f) a = PI_F - a;
    return (y < 0.0f) ? (TWO_PI_F - a) : a;
}

__global__ __launch_bounds__(256) void sc_phase1(
    const float* __restrict__ trajs,      // [B, 8, 2]
    const float* __restrict__ nei_trajs,  // [B, 128, 8, 2]
    float* __restrict__ out_dir)          // [B, 128]
{
    const int n    = threadIdx.x;          // 0..255
    const int row  = n >> 7;               // which batch row in this CTA
    const int ln   = n & 127;
    const int wid  = (n >> 5) & 3;         // warp within row
    const int lane = n & 31;

    const int b = blockIdx.x * 2 + row;

    // obs vector (uniform per row-half -> broadcast loads)
    const float* tb = trajs + (size_t)b * 16;
    const float ox7 = tb[14], oy7 = tb[15];
    const float ovx = ox7 - tb[0];
    const float ovy = oy7 - tb[1];
    const float obs_len = approx_len(ovx * ovx + ovy * ovy);

    // 64B contiguous per thread
    const float4* np4 = (const float4*)(nei_trajs + ((size_t)b * NNEI + ln) * 16);
    const float4 v0 = np4[0];
    const float4 v1 = np4[1];
    const float4 v2 = np4[2];
    const float4 v3 = np4[3];

    const float ssum = (v0.x + v0.y + v0.z + v0.w)
                     + (v1.x + v1.y + v1.z + v1.w)
                     + (v2.x + v2.y + v2.z + v2.w)
                     + (v3.x + v3.y + v3.z + v3.w);
    const bool valid = (ssum != 0.0f);

    const float nvx = v3.z - v0.x;
    const float nvy = v3.w - v0.y;
    const float nei_len = approx_len(nvx * nvx + nvy * nvy);
    const float f_speed = __fdividef(nei_len + MU_F, obs_len + MU_F);

    const float px = v3.z - ox7;
    const float py = v3.w - oy7;
    const float f_dist = approx_len(px * px + py * py);

    const float d = atan2_2pi(py, px);

    out_dir[(size_t)b * NNEI + ln] = d;

    // bucket key: exact IEEE division (boundary-sensitive); invalid or
    // idx==PARTS -> -1 (never matches any ballot below)
    const int idx = (int)(d / (TWO_PI_F / PARTS));
    const int key = (valid && idx < PARTS) ? idx : -1;

    // lane -> (partition p = lane>>2, quarter r = lane&3); m = membership
    // mask of partition p across this warp's 32 neighbors
    const int p = lane >> 2;
    const int r = lane & 3;
    unsigned m = 0;
    #pragma unroll
    for (int pi = 0; pi < PARTS; pi++) {
        const unsigned bm = __ballot_sync(0xffffffffu, key == pi);
        if (p == pi) m = bm;
    }

    // quarter-split gather: lane r scans bits [8r, 8r+8); values fetched by
    // shuffle. Convergent loop (any_sync), guarded accumulate; dummy source
    // lane 0 only when this lane's quarter is exhausted.
    unsigned mq = (m >> (r << 3)) & 0xffu;
    float s = 0.0f, dd = 0.0f, dir = 0.0f;
    while (__any_sync(0xffffffffu, mq != 0u)) {
        const int j = mq ? ((r << 3) + __ffs(mq) - 1) : 0;
        const float a0 = __shfl_sync(0xffffffffu, f_speed, j);
        const float a1 = __shfl_sync(0xffffffffu, f_dist,  j);
        const float a2 = __shfl_sync(0xffffffffu, d,       j);
        if (mq != 0u) {
            s   += a0;
            dd  += a1;
            dir += a2;
            mq &= mq - 1u;
        }
    }

    // combine the 4 quarters (aligned groups of 4 lanes)
    #pragma unroll
    for (int off = 2; off > 0; off >>= 1) {
        s   += __shfl_down_sync(0xffffffffu, s,   off, 4);
        dd  += __shfl_down_sync(0xffffffffu, dd,  off, 4);
        dir += __shfl_down_sync(0xffffffffu, dir, off, 4);
    }
    const float cnt = (float)__popc(m);   // full-warp partition count, free

    // leaders (r==0): 8 lanes store consecutive float4 -> one 128B transaction
    if (r == 0) {
        g_scratch[((size_t)b << 5) + (wid << 3) + p] = make_float4(s, dd, dir, cnt);
    }
}

__global__ __launch_bounds__(256) void sc_phase2(
    float* __restrict__ out_sc)           // [B, 8, 3]
{
    const int warp = threadIdx.x >> 5;
    const int lane = threadIdx.x & 31;
    const int b = blockIdx.x * 8 + warp;

    // lane -> (partition p = lane>>2, source warp r = lane&3); 512B/row coalesced
    const int p = lane >> 2;
    const int r = lane & 3;
    const float4 a = g_scratch[((size_t)b << 5) + (r << 3) + p];
    float s = a.x, dd = a.y, dir = a.z, cnt = a.w;

    #pragma unroll
    for (int off = 2; off > 0; off >>= 1) {
        s   += __shfl_down_sync(0xffffffffu, s,   off, 4);
        dd  += __shfl_down_sync(0xffffffffu, dd,  off, 4);
        dir += __shfl_down_sync(0xffffffffu, dir, off, 4);
        cnt += __shfl_down_sync(0xffffffffu, cnt, off, 4);
    }

    const float inv = __fdividef(1.0f, cnt + CEPS_F);
    s   *= inv;
    dd  *= inv;
    dir *= inv;

    // redistribute so lanes 0..23 emit one coalesced 96B store
    const int p2  = (lane * 11) >> 5;     // lane/3 for lane<32
    const int f   = lane - p2 * 3;
    const int src = p2 << 2;
    const float a0 = __shfl_sync(0xffffffffu, s,   src);
    const float a1 = __shfl_sync(0xffffffffu, dd,  src);
    const float a2 = __shfl_sync(0xffffffffu, dir, src);
    const float outv = (f == 0) ? a0 : ((f == 1) ? a1 : a2);
    if (lane < PARTS * 3) {
        out_sc[(size_t)b * (PARTS * 3) + lane] = outv;
    }
}

extern "C" void kernel_launch(void* const* d_in, const int* in_sizes, int n_in,
                              void* d_out, int out_size) {
    const float* trajs     = (const float*)d_in[0];
    const float* nei_trajs = (const float*)d_in[1];
    float* out = (float*)d_out;

    const int B = in_sizes[0] / 16;   // trajs is [B, 8, 2]

    float* out_sc  = out;                          // [B, 8, 3]
    float* out_dir = out + (size_t)B * PARTS * 3;  // [B, 128]

    sc_phase1<<<B / 2, 256>>>(trajs, nei_trajs, out_dir);
    sc_phase2<<<B / 8, 256>>>(out_sc);
}

// round 14
// speedup vs baseline: 1.0543x; 1.0543x over previous
#include <cuda_runtime.h>

// SocialCircleLayer: B=8192 rows, N=128 neighbors, T=8, P=8.
// R14: phase 1 unchanged from R13 (15.4us, 59% DRAM duty — barrier-free
// streaming confirmed better than any barrier variant). Phase 2 rewritten:
// R13's was a 5.15us MLP=1 latency chain (1 load -> 17 shuffles -> store).
// Now one thread per (row,partition): 4 independent LDG.128 (MLP=4, fully
// coalesced), register sums, no shuffles/smem, 3 contiguous STG.32.

#define NNEI   128
#define PARTS  8
#define MU_F     1e-4f
#define CEPS_F   1e-4f
#define TWO_PI_F 6.283185307179586f
#define PI_F     3.14159265358979f
#define PIO2_F   1.5707963267949f
#define PIO4_F   0.78539816339745f
#define TAN_PIO8 0.41421356237f
#define MAX_B  8192

__device__ float4 g_scratch[MAX_B * 32];   // [B][4 warps][8 parts]

__device__ __forceinline__ float approx_len(float x2) {
    float r;
    asm("rsqrt.approx.f32 %0, %1;" : "=f"(r) : "f"(x2));
    float len = x2 * r;
    return (x2 > 0.0f) ? len : 0.0f;
}

// atan2 in [0, 2*pi): |err| < ~3e-7 rad (validated: rel_err 6.6e-8).
__device__ __forceinline__ float atan2_2pi(float y, float x) {
    const float ax = fabsf(x);
    const float ay = fabsf(y);
    const float mx = fmaxf(ax, ay);
    const float mn = fminf(ax, ay);
    float t = (mx == 0.0f) ? 0.0f : __fdividef(mn, mx);

    const bool red = (t > TAN_PIO8);
    const float u  = red ? __fdividef(t - 1.0f, t + 1.0f) : t;

    const float z = u * u;
    float q;
    q = -1.0f / 15.0f;
    q = fmaf(q, z,  1.0f / 13.0f);
    q = fmaf(q, z, -1.0f / 11.0f);
    q = fmaf(q, z,  1.0f /  9.0f);
    q = fmaf(q, z, -1.0f /  7.0f);
    q = fmaf(q, z,  1.0f /  5.0f);
    q = fmaf(q, z, -1.0f /  3.0f);
    float a = fmaf(q * z, u, u);          // atan(u)

    if (red)      a += PIO4_F;
    if (ay > ax)  a = PIO2_F - a;
    if (x < 0.0f) a = PI_F - a;
    return (y < 0.0f) ? (TWO_PI_F - a) : a;
}

__global__ __launch_bounds__(256) void sc_phase1(
    const float* __restrict__ trajs,      // [B, 8, 2]
    const float* __restrict__ nei_trajs,  // [B, 128, 8, 2]
    float* __restrict__ out_dir)          // [B, 128]
{
    const int n    = threadIdx.x;          // 0..255
    const int row  = n >> 7;               // which batch row in this CTA
    const int ln   = n & 127;
    const int wid  = (n >> 5) & 3;         // warp within row
    const int lane = n & 31;

    const int b = blockIdx.x * 2 + row;

    // obs vector (uniform per row-half -> broadcast loads)
    const float* tb = trajs + (size_t)b * 16;
    const float ox7 = tb[14], oy7 = tb[15];
    const float ovx = ox7 - tb[0];
    const float ovy = oy7 - tb[1];
    const float obs_len = approx_len(ovx * ovx + ovy * ovy);

    // 64B contiguous per thread
    const float4* np4 = (const float4*)(nei_trajs + ((size_t)b * NNEI + ln) * 16);
    const float4 v0 = np4[0];
    const float4 v1 = np4[1];
    const float4 v2 = np4[2];
    const float4 v3 = np4[3];

    const float ssum = (v0.x + v0.y + v0.z + v0.w)
                     + (v1.x + v1.y + v1.z + v1.w)
                     + (v2.x + v2.y + v2.z + v2.w)
                     + (v3.x + v3.y + v3.z + v3.w);
    const bool valid = (ssum != 0.0f);

    const float nvx = v3.z - v0.x;
    const float nvy = v3.w - v0.y;
    const float nei_len = approx_len(nvx * nvx + nvy * nvy);
    const float f_speed = __fdividef(nei_len + MU_F, obs_len + MU_F);

    const float px = v3.z - ox7;
    const float py = v3.w - oy7;
    const float f_dist = approx_len(px * px + py * py);

    const float d = atan2_2pi(py, px);

    out_dir[(size_t)b * NNEI + ln] = d;

    // bucket key: exact IEEE division (boundary-sensitive); invalid or
    // idx==PARTS -> -1 (never matches any ballot below)
    const int idx = (int)(d / (TWO_PI_F / PARTS));
    const int key = (valid && idx < PARTS) ? idx : -1;

    // lane -> (partition p = lane>>2, quarter r = lane&3); m = membership
    // mask of partition p across this warp's 32 neighbors
    const int p = lane >> 2;
    const int r = lane & 3;
    unsigned m = 0;
    #pragma unroll
    for (int pi = 0; pi < PARTS; pi++) {
        const unsigned bm = __ballot_sync(0xffffffffu, key == pi);
        if (p == pi) m = bm;
    }

    // quarter-split gather: lane r scans bits [8r, 8r+8); values fetched by
    // shuffle. Convergent loop (any_sync), guarded accumulate.
    unsigned mq = (m >> (r << 3)) & 0xffu;
    float s = 0.0f, dd = 0.0f, dir = 0.0f;
    while (__any_sync(0xffffffffu, mq != 0u)) {
        const int j = mq ? ((r << 3) + __ffs(mq) - 1) : 0;
        const float a0 = __shfl_sync(0xffffffffu, f_speed, j);
        const float a1 = __shfl_sync(0xffffffffu, f_dist,  j);
        const float a2 = __shfl_sync(0xffffffffu, d,       j);
        if (mq != 0u) {
            s   += a0;
            dd  += a1;
            dir += a2;
            mq &= mq - 1u;
        }
    }

    // combine the 4 quarters (aligned groups of 4 lanes)
    #pragma unroll
    for (int off = 2; off > 0; off >>= 1) {
        s   += __shfl_down_sync(0xffffffffu, s,   off, 4);
        dd  += __shfl_down_sync(0xffffffffu, dd,  off, 4);
        dir += __shfl_down_sync(0xffffffffu, dir, off, 4);
    }
    const float cnt = (float)__popc(m);   // full-warp partition count, free

    // leaders (r==0): 8 lanes store consecutive float4 -> one 128B transaction
    if (r == 0) {
        g_scratch[((size_t)b << 5) + (wid << 3) + p] = make_float4(s, dd, dir, cnt);
    }
}

// One thread per (row, partition). 4 independent LDG.128, register combine.
__global__ __launch_bounds__(256) void sc_phase2(
    float* __restrict__ out_sc)           // [B, 8, 3]
{
    const int tid = blockIdx.x * 256 + threadIdx.x;   // 0 .. B*8-1
    const int b = tid >> 3;
    const int p = tid & 7;

    const float4* base = &g_scratch[((size_t)b << 5) + p];
    const float4 a0 = base[0];     // warp 0 partial
    const float4 a1 = base[8];     // warp 1
    const float4 a2 = base[16];    // warp 2
    const float4 a3 = base[24];    // warp 3

    const float s   = (a0.x + a1.x) + (a2.x + a3.x);
    const float dd  = (a0.y + a1.y) + (a2.y + a3.y);
    const float dir = (a0.z + a1.z) + (a2.z + a3.z);
    const float cnt = (a0.w + a1.w) + (a2.w + a3.w);

    const float inv = __fdividef(1.0f, cnt + CEPS_F);
    float* o = out_sc + (size_t)b * (PARTS * 3) + p * 3;
    o[0] = s   * inv;
    o[1] = dd  * inv;
    o[2] = dir * inv;
}

extern "C" void kernel_launch(void* const* d_in, const int* in_sizes, int n_in,
                              void* d_out, int out_size) {
    const float* trajs     = (const float*)d_in[0];
    const float* nei_trajs = (const float*)d_in[1];
    float* out = (float*)d_out;

    const int B = in_sizes[0] / 16;   // trajs is [B, 8, 2]

    float* out_sc  = out;                          // [B, 8, 3]
    float* out_dir = out + (size_t)B * PARTS * 3;  // [B, 128]

    sc_phase1<<<B / 2, 256>>>(trajs, nei_trajs, out_dir);
    sc_phase2<<<(B * PARTS) / 256, 256>>>(out_sc);
}

// round 15
// speedup vs baseline: 1.0976x; 1.0411x over previous
#include <cuda_runtime.h>

// SocialCircleLayer: B=8192 rows, N=128 neighbors, T=8, P=8.
// R15: fuse the two winners. Phase 1 = R13's streaming body (warp-internal
// bucketed reduction: 8 ballots -> quarter ffs/shfl gather -> width-4 tree;
// measured 15.4us/59% duty, beats every smem-round-trip variant). Combine =
// in-CTA via 1KB smem + one barrier + R8's featherweight tail (2 LDS,
// 8 SHFL, 1 coalesced STG) — NOT a second kernel (R14 proved the split has
// a ~4.5us launch/drain floor) and NOT the 9-iter ffs-LDS tail of R8.

#define NNEI   128
#define PARTS  8
#define ROWS_PER_CTA 2
#define MU_F     1e-4f
#define CEPS_F   1e-4f
#define TWO_PI_F 6.283185307179586f
#define PI_F     3.14159265358979f
#define PIO2_F   1.5707963267949f
#define PIO4_F   0.78539816339745f
#define TAN_PIO8 0.41421356237f

__device__ __forceinline__ float approx_len(float x2) {
    float r;
    asm("rsqrt.approx.f32 %0, %1;" : "=f"(r) : "f"(x2));
    float len = x2 * r;
    return (x2 > 0.0f) ? len : 0.0f;
}

// atan2 in [0, 2*pi): |err| < ~3e-7 rad (validated: rel_err 6.8e-8).
__device__ __forceinline__ float atan2_2pi(float y, float x) {
    const float ax = fabsf(x);
    const float ay = fabsf(y);
    const float mx = fmaxf(ax, ay);
    const float mn = fminf(ax, ay);
    float t = (mx == 0.0f) ? 0.0f : __fdividef(mn, mx);

    const bool red = (t > TAN_PIO8);
    const float u  = red ? __fdividef(t - 1.0f, t + 1.0f) : t;

    const float z = u * u;
    float q;
    q = -1.0f / 15.0f;
    q = fmaf(q, z,  1.0f / 13.0f);
    q = fmaf(q, z, -1.0f / 11.0f);
    q = fmaf(q, z,  1.0f /  9.0f);
    q = fmaf(q, z, -1.0f /  7.0f);
    q = fmaf(q, z,  1.0f /  5.0f);
    q = fmaf(q, z, -1.0f /  3.0f);
    float a = fmaf(q * z, u, u);          // atan(u)

    if (red)      a += PIO4_F;
    if (ay > ax)  a = PIO2_F - a;
    if (x < 0.0f) a = PI_F - a;
    return (y < 0.0f) ? (TWO_PI_F - a) : a;
}

__global__ __launch_bounds__(NNEI * ROWS_PER_CTA) void social_circle_kernel(
    const float* __restrict__ trajs,      // [B, 8, 2]
    const float* __restrict__ nei_trajs,  // [B, 128, 8, 2]
    float* __restrict__ out_sc,           // [B, 8, 3]
    float* __restrict__ out_dir)          // [B, 128]
{
    const int n    = threadIdx.x;          // 0..255
    const int row  = n >> 7;               // which batch row in this CTA
    const int ln   = n & 127;
    const int wid  = (n >> 5) & 3;         // warp within row
    const int lane = n & 31;

    const int b = blockIdx.x * ROWS_PER_CTA + row;

    // per-warp per-partition partials: {sum_speed, sum_dist, sum_dir, count}
    __shared__ float4 acc[ROWS_PER_CTA][4][PARTS];   // 1 KB

    // obs vector (uniform per row-half -> broadcast loads)
    const float* tb = trajs + (size_t)b * 16;
    const float ox7 = tb[14], oy7 = tb[15];
    const float ovx = ox7 - tb[0];
    const float ovy = oy7 - tb[1];
    const float obs_len = approx_len(ovx * ovx + ovy * ovy);

    // 64B contiguous per thread
    const float4* np4 = (const float4*)(nei_trajs + ((size_t)b * NNEI + ln) * 16);
    const float4 v0 = np4[0];
    const float4 v1 = np4[1];
    const float4 v2 = np4[2];
    const float4 v3 = np4[3];

    const float ssum = (v0.x + v0.y + v0.z + v0.w)
                     + (v1.x + v1.y + v1.z + v1.w)
                     + (v2.x + v2.y + v2.z + v2.w)
                     + (v3.x + v3.y + v3.z + v3.w);
    const bool valid = (ssum != 0.0f);

    const float nvx = v3.z - v0.x;
    const float nvy = v3.w - v0.y;
    const float nei_len = approx_len(nvx * nvx + nvy * nvy);
    const float f_speed = __fdividef(nei_len + MU_F, obs_len + MU_F);

    const float px = v3.z - ox7;
    const float py = v3.w - oy7;
    const float f_dist = approx_len(px * px + py * py);

    const float d = atan2_2pi(py, px);

    out_dir[(size_t)b * NNEI + ln] = d;

    // bucket key: exact IEEE division (boundary-sensitive); invalid or
    // idx==PARTS -> -1 (never matches any ballot below)
    const int idx = (int)(d / (TWO_PI_F / PARTS));
    const int key = (valid && idx < PARTS) ? idx : -1;

    // lane -> (partition p = lane>>2, quarter r = lane&3); m = membership
    // mask of partition p across this warp's 32 neighbors
    const int p = lane >> 2;
    const int r = lane & 3;
    unsigned m = 0;
    #pragma unroll
    for (int pi = 0; pi < PARTS; pi++) {
        const unsigned bm = __ballot_sync(0xffffffffu, key == pi);
        if (p == pi) m = bm;
    }

    // quarter-split gather: lane r scans bits [8r, 8r+8); values fetched by
    // shuffle (register file). Convergent loop, guarded accumulate.
    unsigned mq = (m >> (r << 3)) & 0xffu;
    float s = 0.0f, dd = 0.0f, dir = 0.0f;
    while (__any_sync(0xffffffffu, mq != 0u)) {
        const int j = mq ? ((r << 3) + __ffs(mq) - 1) : 0;
        const float a0 = __shfl_sync(0xffffffffu, f_speed, j);
        const float a1 = __shfl_sync(0xffffffffu, f_dist,  j);
        const float a2 = __shfl_sync(0xffffffffu, d,       j);
        if (mq != 0u) {
            s   += a0;
            dd  += a1;
            dir += a2;
            mq &= mq - 1u;
        }
    }

    // combine the 4 quarters (aligned groups of 4 lanes)
    #pragma unroll
    for (int off = 2; off > 0; off >>= 1) {
        s   += __shfl_down_sync(0xffffffffu, s,   off, 4);
        dd  += __shfl_down_sync(0xffffffffu, dd,  off, 4);
        dir += __shfl_down_sync(0xffffffffu, dir, off, 4);
    }
    const float cnt = (float)__popc(m);   // full-warp partition count, free

    // leaders (r==0): 8 lanes store consecutive float4 -> 1 smem wavefront
    if (r == 0) {
        acc[row][wid][p] = make_float4(s, dd, dir, cnt);
    }
    __syncthreads();

    // Featherweight combine: warp w (< ROWS_PER_CTA) finishes row w.
    // lane -> (partition p2 = lane>>2, source warp r2 = lane&3).
    if (n < 32 * ROWS_PER_CTA) {
        const int rw = n >> 5;             // row this warp reduces
        const int pp = lane >> 2;
        const int rr = lane & 3;
        const int bb = blockIdx.x * ROWS_PER_CTA + rw;

        const float4 a = acc[rw][rr][pp];  // 32 distinct float4 (4 wavefronts)
        float s2 = a.x, dd2 = a.y, dir2 = a.z, cnt2 = a.w;

        #pragma unroll
        for (int off = 2; off > 0; off >>= 1) {
            s2   += __shfl_down_sync(0xffffffffu, s2,   off, 4);
            dd2  += __shfl_down_sync(0xffffffffu, dd2,  off, 4);
            dir2 += __shfl_down_sync(0xffffffffu, dir2, off, 4);
            cnt2 += __shfl_down_sync(0xffffffffu, cnt2, off, 4);
        }

        const float inv = __fdividef(1.0f, cnt2 + CEPS_F);
        s2   *= inv;
        dd2  *= inv;
        dir2 *= inv;

        // redistribute so lanes 0..23 emit one coalesced 96B store per row
        const int p2  = (lane * 11) >> 5;   // lane/3 for lane<32
        const int f   = lane - p2 * 3;
        const int src = p2 << 2;            // leader lane of partition p2
        const float a0 = __shfl_sync(0xffffffffu, s2,   src);
        const float a1 = __shfl_sync(0xffffffffu, dd2,  src);
        const float a2 = __shfl_sync(0xffffffffu, dir2, src);
        const float outv = (f == 0) ? a0 : ((f == 1) ? a1 : a2);
        if (lane < PARTS * 3) {
            out_sc[(size_t)bb * (PARTS * 3) + lane] = outv;
        }
    }
}

extern "C" void kernel_launch(void* const* d_in, const int* in_sizes, int n_in,
                              void* d_out, int out_size) {
    const float* trajs     = (const float*)d_in[0];
    const float* nei_trajs = (const float*)d_in[1];
    float* out = (float*)d_out;

    const int B = in_sizes[0] / 16;   // trajs is [B, 8, 2]

    float* out_sc  = out;                          // [B, 8, 3]
    float* out_dir = out + (size_t)B * PARTS * 3;  // [B, 128]

    social_circle_kernel<<<B / ROWS_PER_CTA, NNEI * ROWS_PER_CTA>>>(
        trajs, nei_trajs, out_sc, out_dir);
}